// round 4
// baseline (speedup 1.0000x reference)
#include <cuda_runtime.h>
#include <cstdint>

#define N_POI_C  100000
#define N_EDGE_C 50000
#define NNZ_MAX  3200000
#define EMB      128

// ---------------- scratch (static device globals; no allocation) ----------------
__device__ int   g_cnt[N_POI_C];
__device__ int   g_rowptr[N_POI_C + 1];
__device__ int   g_cursor[N_POI_C];
__device__ int2  g_pack[NNZ_MAX];                       // (col, val-as-bits)
__device__ float g_S1[(size_t)N_EDGE_C * EMB];          // spmm(pte, poi_embs)
__device__ float g_Wc1[EMB * EMB];                      // W_poi  @ Wf[0:128]
__device__ float g_Wc2[EMB * EMB];                      // W_edge @ Wf[128:256]

// ---------------- tiny weight-fold GEMMs: Wc1/Wc2 (128x128 each) ----------------
__global__ void wc_kernel(const float* __restrict__ Wp,
                          const float* __restrict__ We,
                          const float* __restrict__ Wf) {
    __shared__ float srow[EMB];
    int i = blockIdx.x;            // output row
    int j = threadIdx.x;           // output col
    const float* W  = blockIdx.y ? We : Wp;
    const float* Bf = Wf + (blockIdx.y ? EMB * EMB : 0);
    srow[j] = W[i * EMB + j];
    __syncthreads();
    float acc = 0.f;
#pragma unroll 8
    for (int k = 0; k < EMB; ++k)
        acc = fmaf(srow[k], Bf[k * EMB + j], acc);
    (blockIdx.y ? g_Wc2 : g_Wc1)[i * EMB + j] = acc;
}

// ---------------- CSR build ----------------
__global__ void zero_kernel(int n) {
    for (int i = blockIdx.x * blockDim.x + threadIdx.x; i < n;
         i += gridDim.x * blockDim.x)
        g_cnt[i] = 0;
}

__global__ void hist_kernel(const int* __restrict__ rows, int nnz) {
    for (int i = blockIdx.x * blockDim.x + threadIdx.x; i < nnz;
         i += gridDim.x * blockDim.x)
        atomicAdd(&g_cnt[rows[i]], 1);
}

// single-block chunked exclusive scan (shuffle-based, ~3 barriers per 1024 chunk)
__global__ void scan_kernel(int n) {
    __shared__ int warp_sums[32];
    __shared__ int s_carry;
    int tid = threadIdx.x;              // 1024 threads
    int lane = tid & 31, wid = tid >> 5;
    if (tid == 0) s_carry = 0;
    __syncthreads();
    for (int base = 0; base < n; base += 1024) {
        int i = base + tid;
        int v = (i < n) ? g_cnt[i] : 0;
        int x = v;
#pragma unroll
        for (int d = 1; d < 32; d <<= 1) {
            int t = __shfl_up_sync(0xFFFFFFFFu, x, d);
            if (lane >= d) x += t;
        }
        if (lane == 31) warp_sums[wid] = x;
        __syncthreads();
        if (wid == 0) {
            int w = warp_sums[lane];
#pragma unroll
            for (int d = 1; d < 32; d <<= 1) {
                int t = __shfl_up_sync(0xFFFFFFFFu, w, d);
                if (lane >= d) w += t;
            }
            warp_sums[lane] = w;        // inclusive across warps
        }
        __syncthreads();
        int warp_off = (wid == 0) ? 0 : warp_sums[wid - 1];
        int incl = x + warp_off + s_carry;
        int excl = incl - v;
        if (i < n) { g_rowptr[i] = excl; g_cursor[i] = excl; }
        __syncthreads();
        if (tid == 1023) s_carry = incl;
        __syncthreads();
    }
    if (tid == 0) g_rowptr[n] = s_carry;
}

__global__ void scatter_kernel(const int* __restrict__ rows,
                               const int* __restrict__ cols,
                               const float* __restrict__ vals, int nnz) {
    for (int i = blockIdx.x * blockDim.x + threadIdx.x; i < nnz;
         i += gridDim.x * blockDim.x) {
        int r = rows[i];
        int pos = atomicAdd(&g_cursor[r], 1);
        g_pack[pos] = make_int2(cols[i], __float_as_int(vals[i]));
    }
}

// ---------------- CSR SpMM: one warp per output row, float4 per lane ----------------
// out == nullptr -> write to g_S1
__global__ __launch_bounds__(128) void spmm_kernel(const float* __restrict__ dense,
                                                   float* __restrict__ out,
                                                   int nrows) {
    int r = blockIdx.x * 4 + (threadIdx.x >> 5);
    if (r >= nrows) return;
    int lane = threadIdx.x & 31;
    int s = __ldg(&g_rowptr[r]);
    int e = __ldg(&g_rowptr[r + 1]);
    float* o = out ? out : (float*)g_S1;
    float4 acc = make_float4(0.f, 0.f, 0.f, 0.f);
    int j = s;
    for (; j + 4 <= e; j += 4) {
        int2 p0 = __ldg(&g_pack[j + 0]);
        int2 p1 = __ldg(&g_pack[j + 1]);
        int2 p2 = __ldg(&g_pack[j + 2]);
        int2 p3 = __ldg(&g_pack[j + 3]);
        float4 d0 = __ldg((const float4*)(dense + (size_t)p0.x * EMB) + lane);
        float4 d1 = __ldg((const float4*)(dense + (size_t)p1.x * EMB) + lane);
        float4 d2 = __ldg((const float4*)(dense + (size_t)p2.x * EMB) + lane);
        float4 d3 = __ldg((const float4*)(dense + (size_t)p3.x * EMB) + lane);
        float v0 = __int_as_float(p0.y), v1 = __int_as_float(p1.y);
        float v2 = __int_as_float(p2.y), v3 = __int_as_float(p3.y);
        acc.x = fmaf(v0, d0.x, acc.x); acc.y = fmaf(v0, d0.y, acc.y);
        acc.z = fmaf(v0, d0.z, acc.z); acc.w = fmaf(v0, d0.w, acc.w);
        acc.x = fmaf(v1, d1.x, acc.x); acc.y = fmaf(v1, d1.y, acc.y);
        acc.z = fmaf(v1, d1.z, acc.z); acc.w = fmaf(v1, d1.w, acc.w);
        acc.x = fmaf(v2, d2.x, acc.x); acc.y = fmaf(v2, d2.y, acc.y);
        acc.z = fmaf(v2, d2.z, acc.z); acc.w = fmaf(v2, d2.w, acc.w);
        acc.x = fmaf(v3, d3.x, acc.x); acc.y = fmaf(v3, d3.y, acc.y);
        acc.z = fmaf(v3, d3.z, acc.z); acc.w = fmaf(v3, d3.w, acc.w);
    }
    for (; j < e; ++j) {
        int2 p = __ldg(&g_pack[j]);
        float4 d = __ldg((const float4*)(dense + (size_t)p.x * EMB) + lane);
        float v = __int_as_float(p.y);
        acc.x = fmaf(v, d.x, acc.x); acc.y = fmaf(v, d.y, acc.y);
        acc.z = fmaf(v, d.z, acc.z); acc.w = fmaf(v, d.w, acc.w);
    }
    *(float4*)(o + (size_t)r * EMB + lane * 4) = acc;
}

// ---------------- fused edge GEMM: F = g_S1 @ Wc1 + E @ Wc2 ----------------
// 64-row tiles, 256 threads, 8x4 microtile per thread, BK=32, K=256 (2 sources).
__global__ __launch_bounds__(256) void fused_gemm_kernel(const float* __restrict__ E,
                                                         float* __restrict__ F,
                                                         int nrows) {
    __shared__ __align__(16) float sA[32][65];   // transposed A chunk [k][m]
    __shared__ __align__(16) float sB[32][128];
    int tid = threadIdx.x;
    int tr = tid >> 5;          // row group 0..7 (8 rows each)
    int tc = tid & 31;          // col group 0..31 (4 cols each)
    int row0 = blockIdx.x * 64;
    float acc[8][4];
#pragma unroll
    for (int i = 0; i < 8; ++i)
#pragma unroll
        for (int c = 0; c < 4; ++c) acc[i][c] = 0.f;

#pragma unroll 1
    for (int chunk = 0; chunk < 8; ++chunk) {
        const float* A = (chunk < 4) ? (const float*)g_S1 : E;
        const float* B = (chunk < 4) ? (const float*)g_Wc1 : (const float*)g_Wc2;
        int k0 = (chunk & 3) * 32;
        // load 64x32 A chunk (transposed into sA)
#pragma unroll
        for (int q = 0; q < 2; ++q) {
            int lin = tid * 2 + q;          // 0..511
            int m   = lin >> 3;             // 0..63
            int kk  = (lin & 7) << 2;       // 0..28 step 4
            float4 a4 = make_float4(0.f, 0.f, 0.f, 0.f);
            if (row0 + m < nrows)
                a4 = *(const float4*)(A + (size_t)(row0 + m) * EMB + k0 + kk);
            sA[kk + 0][m] = a4.x; sA[kk + 1][m] = a4.y;
            sA[kk + 2][m] = a4.z; sA[kk + 3][m] = a4.w;
        }
        // load 32x128 B chunk
#pragma unroll
        for (int q = 0; q < 4; ++q) {
            int lin = tid * 4 + q;          // 0..1023 float4 slots
            int k = lin >> 5, c4 = lin & 31;
            *(float4*)(&sB[k][c4 * 4]) =
                *(const float4*)(B + (size_t)(k0 + k) * EMB + c4 * 4);
        }
        __syncthreads();
#pragma unroll
        for (int k = 0; k < 32; ++k) {
            float4 b = *(const float4*)(&sB[k][tc * 4]);
#pragma unroll
            for (int i = 0; i < 8; ++i) {
                float a = sA[k][tr * 8 + i];
                acc[i][0] = fmaf(a, b.x, acc[i][0]);
                acc[i][1] = fmaf(a, b.y, acc[i][1]);
                acc[i][2] = fmaf(a, b.z, acc[i][2]);
                acc[i][3] = fmaf(a, b.w, acc[i][3]);
            }
        }
        __syncthreads();
    }
#pragma unroll
    for (int i = 0; i < 8; ++i) {
        int r = row0 + tr * 8 + i;
        if (r < nrows)
            *(float4*)(F + (size_t)r * EMB + tc * 4) =
                make_float4(acc[i][0], acc[i][1], acc[i][2], acc[i][3]);
    }
}

// ---------------- launch ----------------
extern "C" void kernel_launch(void* const* d_in, const int* in_sizes, int n_in,
                              void* d_out, int out_size) {
    const float* poi  = (const float*)d_in[0];
    const float* edge = (const float*)d_in[1];
    const int*   pr   = (const int*)d_in[2];
    const int*   pc   = (const int*)d_in[3];
    const float* pv   = (const float*)d_in[4];
    const int*   er   = (const int*)d_in[5];
    const int*   ec   = (const int*)d_in[6];
    const float* ev   = (const float*)d_in[7];
    const float* Wp   = (const float*)d_in[8];
    const float* We   = (const float*)d_in[9];
    const float* Wf   = (const float*)d_in[10];
    int nnz1 = in_sizes[2];
    int nnz2 = in_sizes[5];

    float* prop = (float*)d_out;                       // [100000, 128]
    float* F    = prop + (size_t)N_POI_C * EMB;        // [50000, 128]

    // fold weights (independent of everything else)
    wc_kernel<<<dim3(128, 2), 128>>>(Wp, We, Wf);

    // --- SpMM 1: S1 = pte @ poi_embs ---
    zero_kernel<<<256, 256>>>(N_EDGE_C);
    hist_kernel<<<2048, 256>>>(pr, nnz1);
    scan_kernel<<<1, 1024>>>(N_EDGE_C);
    scatter_kernel<<<2048, 256>>>(pr, pc, pv, nnz1);
    spmm_kernel<<<(N_EDGE_C + 3) / 4, 128>>>(poi, nullptr, N_EDGE_C);

    // --- fused edge features: F = S1@Wc1 + edge@Wc2 ---
    fused_gemm_kernel<<<(N_EDGE_C + 63) / 64, 256>>>(edge, F, N_EDGE_C);

    // --- SpMM 2: prop = etp @ F ---
    zero_kernel<<<256, 256>>>(N_POI_C);
    hist_kernel<<<2048, 256>>>(er, nnz2);
    scan_kernel<<<1, 1024>>>(N_POI_C);
    scatter_kernel<<<2048, 256>>>(er, ec, ev, nnz2);
    spmm_kernel<<<(N_POI_C + 3) / 4, 128>>>(F, prop, N_POI_C);
}

// round 5
// speedup vs baseline: 1.1991x; 1.1991x over previous
#include <cuda_runtime.h>
#include <cstdint>

#define N_POI_C  100000
#define N_EDGE_C 50000
#define NNZ_MAX  3200000
#define EMB      128
#define SCAN_B   1024
#define MAX_SCAN_BLOCKS 128

// ---------------- scratch (static device globals; no allocation) ----------------
__device__ int   g_cnt[N_POI_C];
__device__ int   g_rowptr[N_POI_C + 1];
__device__ int   g_cursor[N_POI_C];
__device__ int   g_bsum[MAX_SCAN_BLOCKS];
__device__ int   g_boff[MAX_SCAN_BLOCKS + 1];
__device__ int2  g_pack[NNZ_MAX];                       // (col, val-as-bits)
__device__ float g_S1[(size_t)N_EDGE_C * EMB];          // spmm(pte, poi_embs)
__device__ float g_Wc1[EMB * EMB];                      // W_poi  @ Wf[0:128]
__device__ float g_Wc2[EMB * EMB];                      // W_edge @ Wf[128:256]

// ---------------- tiny weight-fold GEMMs: Wc1/Wc2 (128x128 each) ----------------
__global__ void wc_kernel(const float* __restrict__ Wp,
                          const float* __restrict__ We,
                          const float* __restrict__ Wf) {
    __shared__ float srow[EMB];
    int i = blockIdx.x;            // output row
    int j = threadIdx.x;           // output col
    const float* W  = blockIdx.y ? We : Wp;
    const float* Bf = Wf + (blockIdx.y ? EMB * EMB : 0);
    srow[j] = W[i * EMB + j];
    __syncthreads();
    float acc = 0.f;
#pragma unroll 8
    for (int k = 0; k < EMB; ++k)
        acc = fmaf(srow[k], Bf[k * EMB + j], acc);
    (blockIdx.y ? g_Wc2 : g_Wc1)[i * EMB + j] = acc;
}

// ---------------- CSR build ----------------
__global__ void zero_kernel(int n) {
    for (int i = blockIdx.x * blockDim.x + threadIdx.x; i < n;
         i += gridDim.x * blockDim.x)
        g_cnt[i] = 0;
}

__global__ void hist_kernel(const int* __restrict__ rows, int nnz) {
    int stride = gridDim.x * blockDim.x;
    int tid = blockIdx.x * blockDim.x + threadIdx.x;
    int n4 = nnz >> 2;
    const int4* r4 = (const int4*)rows;
    for (int i = tid; i < n4; i += stride) {
        int4 r = __ldg(r4 + i);
        atomicAdd(&g_cnt[r.x], 1);
        atomicAdd(&g_cnt[r.y], 1);
        atomicAdd(&g_cnt[r.z], 1);
        atomicAdd(&g_cnt[r.w], 1);
    }
    for (int i = n4 * 4 + tid; i < nnz; i += stride)
        atomicAdd(&g_cnt[rows[i]], 1);
}

// --- multi-block exclusive scan over g_cnt[0..n): 3 passes, all full-chip ---
// pass 1: per-block (1024-elem) sums
__global__ __launch_bounds__(SCAN_B) void scan_pass1(int n) {
    __shared__ int ws[32];
    int tid = threadIdx.x, lane = tid & 31, wid = tid >> 5;
    int i = blockIdx.x * SCAN_B + tid;
    int s = (i < n) ? g_cnt[i] : 0;
#pragma unroll
    for (int d = 16; d > 0; d >>= 1) s += __shfl_down_sync(0xFFFFFFFFu, s, d);
    if (lane == 0) ws[wid] = s;
    __syncthreads();
    if (wid == 0) {
        int t = ws[lane];
#pragma unroll
        for (int d = 16; d > 0; d >>= 1) t += __shfl_down_sync(0xFFFFFFFFu, t, d);
        if (lane == 0) g_bsum[blockIdx.x] = t;
    }
}

// pass 2: single tiny block scans the <=128 block sums (exclusive)
__global__ __launch_bounds__(128) void scan_pass2(int nblocks) {
    __shared__ int ws[4];
    int tid = threadIdx.x, lane = tid & 31, wid = tid >> 5;
    int v = (tid < nblocks) ? g_bsum[tid] : 0;
    int x = v;
#pragma unroll
    for (int d = 1; d < 32; d <<= 1) {
        int t = __shfl_up_sync(0xFFFFFFFFu, x, d);
        if (lane >= d) x += t;
    }
    if (lane == 31) ws[wid] = x;
    __syncthreads();
    int woff = 0;
    for (int w = 0; w < wid; ++w) woff += ws[w];
    int incl = x + woff;
    if (tid <= nblocks) {
        if (tid < nblocks) g_boff[tid] = incl - v;
        if (tid == nblocks - 1) g_boff[nblocks] = incl;
    }
}

// pass 3: per-block inclusive scan + block offset -> rowptr / cursor
__global__ __launch_bounds__(SCAN_B) void scan_pass3(int n) {
    __shared__ int ws[32];
    int tid = threadIdx.x, lane = tid & 31, wid = tid >> 5;
    int i = blockIdx.x * SCAN_B + tid;
    int v = (i < n) ? g_cnt[i] : 0;
    int x = v;
#pragma unroll
    for (int d = 1; d < 32; d <<= 1) {
        int t = __shfl_up_sync(0xFFFFFFFFu, x, d);
        if (lane >= d) x += t;
    }
    if (lane == 31) ws[wid] = x;
    __syncthreads();
    if (wid == 0) {
        int w = ws[lane];
#pragma unroll
        for (int d = 1; d < 32; d <<= 1) {
            int t = __shfl_up_sync(0xFFFFFFFFu, w, d);
            if (lane >= d) w += t;
        }
        ws[lane] = w;
    }
    __syncthreads();
    int woff = wid ? ws[wid - 1] : 0;
    int excl = (x - v) + woff + g_boff[blockIdx.x];
    if (i < n) {
        g_rowptr[i] = excl;
        g_cursor[i] = excl;
        if (i == n - 1) g_rowptr[n] = excl + v;
    }
}

__global__ void scatter_kernel(const int* __restrict__ rows,
                               const int* __restrict__ cols,
                               const float* __restrict__ vals, int nnz) {
    int stride = gridDim.x * blockDim.x;
    int tid = blockIdx.x * blockDim.x + threadIdx.x;
    int n4 = nnz >> 2;
    const int4*   r4 = (const int4*)rows;
    const int4*   c4 = (const int4*)cols;
    const float4* v4 = (const float4*)vals;
    for (int i = tid; i < n4; i += stride) {
        int4 r = __ldg(r4 + i);
        int4 c = __ldg(c4 + i);
        float4 v = __ldg(v4 + i);
        int p0 = atomicAdd(&g_cursor[r.x], 1);
        int p1 = atomicAdd(&g_cursor[r.y], 1);
        int p2 = atomicAdd(&g_cursor[r.z], 1);
        int p3 = atomicAdd(&g_cursor[r.w], 1);
        g_pack[p0] = make_int2(c.x, __float_as_int(v.x));
        g_pack[p1] = make_int2(c.y, __float_as_int(v.y));
        g_pack[p2] = make_int2(c.z, __float_as_int(v.z));
        g_pack[p3] = make_int2(c.w, __float_as_int(v.w));
    }
    for (int i = n4 * 4 + tid; i < nnz; i += stride) {
        int pos = atomicAdd(&g_cursor[rows[i]], 1);
        g_pack[pos] = make_int2(cols[i], __float_as_int(vals[i]));
    }
}

// ---------------- CSR SpMM: one warp per output row, float4 per lane ----------------
// out == nullptr -> write to g_S1
__global__ __launch_bounds__(128) void spmm_kernel(const float* __restrict__ dense,
                                                   float* __restrict__ out,
                                                   int nrows) {
    int r = blockIdx.x * 4 + (threadIdx.x >> 5);
    if (r >= nrows) return;
    int lane = threadIdx.x & 31;
    int s = __ldg(&g_rowptr[r]);
    int e = __ldg(&g_rowptr[r + 1]);
    float* o = out ? out : (float*)g_S1;
    float4 acc = make_float4(0.f, 0.f, 0.f, 0.f);
    int j = s;
    for (; j + 4 <= e; j += 4) {
        int2 p0 = __ldg(&g_pack[j + 0]);
        int2 p1 = __ldg(&g_pack[j + 1]);
        int2 p2 = __ldg(&g_pack[j + 2]);
        int2 p3 = __ldg(&g_pack[j + 3]);
        float4 d0 = __ldg((const float4*)(dense + (size_t)p0.x * EMB) + lane);
        float4 d1 = __ldg((const float4*)(dense + (size_t)p1.x * EMB) + lane);
        float4 d2 = __ldg((const float4*)(dense + (size_t)p2.x * EMB) + lane);
        float4 d3 = __ldg((const float4*)(dense + (size_t)p3.x * EMB) + lane);
        float v0 = __int_as_float(p0.y), v1 = __int_as_float(p1.y);
        float v2 = __int_as_float(p2.y), v3 = __int_as_float(p3.y);
        acc.x = fmaf(v0, d0.x, acc.x); acc.y = fmaf(v0, d0.y, acc.y);
        acc.z = fmaf(v0, d0.z, acc.z); acc.w = fmaf(v0, d0.w, acc.w);
        acc.x = fmaf(v1, d1.x, acc.x); acc.y = fmaf(v1, d1.y, acc.y);
        acc.z = fmaf(v1, d1.z, acc.z); acc.w = fmaf(v1, d1.w, acc.w);
        acc.x = fmaf(v2, d2.x, acc.x); acc.y = fmaf(v2, d2.y, acc.y);
        acc.z = fmaf(v2, d2.z, acc.z); acc.w = fmaf(v2, d2.w, acc.w);
        acc.x = fmaf(v3, d3.x, acc.x); acc.y = fmaf(v3, d3.y, acc.y);
        acc.z = fmaf(v3, d3.z, acc.z); acc.w = fmaf(v3, d3.w, acc.w);
    }
    for (; j < e; ++j) {
        int2 p = __ldg(&g_pack[j]);
        float4 d = __ldg((const float4*)(dense + (size_t)p.x * EMB) + lane);
        float v = __int_as_float(p.y);
        acc.x = fmaf(v, d.x, acc.x); acc.y = fmaf(v, d.y, acc.y);
        acc.z = fmaf(v, d.z, acc.z); acc.w = fmaf(v, d.w, acc.w);
    }
    *(float4*)(o + (size_t)r * EMB + lane * 4) = acc;
}

// ---------------- fused edge GEMM: F = g_S1 @ Wc1 + E @ Wc2 ----------------
// 64-row tiles, 256 threads, 8x4 microtile per thread, BK=32, K=256 (2 sources).
__global__ __launch_bounds__(256) void fused_gemm_kernel(const float* __restrict__ E,
                                                         float* __restrict__ F,
                                                         int nrows) {
    __shared__ __align__(16) float sA[32][65];   // transposed A chunk [k][m]
    __shared__ __align__(16) float sB[32][128];
    int tid = threadIdx.x;
    int tr = tid >> 5;          // row group 0..7 (8 rows each)
    int tc = tid & 31;          // col group 0..31 (4 cols each)
    int row0 = blockIdx.x * 64;
    float acc[8][4];
#pragma unroll
    for (int i = 0; i < 8; ++i)
#pragma unroll
        for (int c = 0; c < 4; ++c) acc[i][c] = 0.f;

#pragma unroll 1
    for (int chunk = 0; chunk < 8; ++chunk) {
        const float* A = (chunk < 4) ? (const float*)g_S1 : E;
        const float* B = (chunk < 4) ? (const float*)g_Wc1 : (const float*)g_Wc2;
        int k0 = (chunk & 3) * 32;
        // load 64x32 A chunk (transposed into sA)
#pragma unroll
        for (int q = 0; q < 2; ++q) {
            int lin = tid * 2 + q;          // 0..511
            int m   = lin >> 3;             // 0..63
            int kk  = (lin & 7) << 2;       // 0..28 step 4
            float4 a4 = make_float4(0.f, 0.f, 0.f, 0.f);
            if (row0 + m < nrows)
                a4 = *(const float4*)(A + (size_t)(row0 + m) * EMB + k0 + kk);
            sA[kk + 0][m] = a4.x; sA[kk + 1][m] = a4.y;
            sA[kk + 2][m] = a4.z; sA[kk + 3][m] = a4.w;
        }
        // load 32x128 B chunk
#pragma unroll
        for (int q = 0; q < 4; ++q) {
            int lin = tid * 4 + q;          // 0..1023 float4 slots
            int k = lin >> 5, c4 = lin & 31;
            *(float4*)(&sB[k][c4 * 4]) =
                *(const float4*)(B + (size_t)(k0 + k) * EMB + c4 * 4);
        }
        __syncthreads();
#pragma unroll
        for (int k = 0; k < 32; ++k) {
            float4 b = *(const float4*)(&sB[k][tc * 4]);
#pragma unroll
            for (int i = 0; i < 8; ++i) {
                float a = sA[k][tr * 8 + i];
                acc[i][0] = fmaf(a, b.x, acc[i][0]);
                acc[i][1] = fmaf(a, b.y, acc[i][1]);
                acc[i][2] = fmaf(a, b.z, acc[i][2]);
                acc[i][3] = fmaf(a, b.w, acc[i][3]);
            }
        }
        __syncthreads();
    }
#pragma unroll
    for (int i = 0; i < 8; ++i) {
        int r = row0 + tr * 8 + i;
        if (r < nrows)
            *(float4*)(F + (size_t)r * EMB + tc * 4) =
                make_float4(acc[i][0], acc[i][1], acc[i][2], acc[i][3]);
    }
}

// ---------------- launch ----------------
static inline void build_csr(const int* rows, const int* cols, const float* vals,
                             int nnz, int nrows) {
    int nblocks = (nrows + SCAN_B - 1) / SCAN_B;
    zero_kernel<<<256, 256>>>(nrows);
    hist_kernel<<<1024, 256>>>(rows, nnz);
    scan_pass1<<<nblocks, SCAN_B>>>(nrows);
    scan_pass2<<<1, 128>>>(nblocks);
    scan_pass3<<<nblocks, SCAN_B>>>(nrows);
    scatter_kernel<<<1024, 256>>>(rows, cols, vals, nnz);
}

extern "C" void kernel_launch(void* const* d_in, const int* in_sizes, int n_in,
                              void* d_out, int out_size) {
    const float* poi  = (const float*)d_in[0];
    const float* edge = (const float*)d_in[1];
    const int*   pr   = (const int*)d_in[2];
    const int*   pc   = (const int*)d_in[3];
    const float* pv   = (const float*)d_in[4];
    const int*   er   = (const int*)d_in[5];
    const int*   ec   = (const int*)d_in[6];
    const float* ev   = (const float*)d_in[7];
    const float* Wp   = (const float*)d_in[8];
    const float* We   = (const float*)d_in[9];
    const float* Wf   = (const float*)d_in[10];
    int nnz1 = in_sizes[2];
    int nnz2 = in_sizes[5];

    float* prop = (float*)d_out;                       // [100000, 128]
    float* F    = prop + (size_t)N_POI_C * EMB;        // [50000, 128]

    // fold weights (independent of everything else)
    wc_kernel<<<dim3(128, 2), 128>>>(Wp, We, Wf);

    // --- SpMM 1: S1 = pte @ poi_embs ---
    build_csr(pr, pc, pv, nnz1, N_EDGE_C);
    spmm_kernel<<<(N_EDGE_C + 3) / 4, 128>>>(poi, nullptr, N_EDGE_C);

    // --- fused edge features: F = S1@Wc1 + edge@Wc2 ---
    fused_gemm_kernel<<<(N_EDGE_C + 63) / 64, 256>>>(edge, F, N_EDGE_C);

    // --- SpMM 2: prop = etp @ F ---
    build_csr(er, ec, ev, nnz2, N_POI_C);
    spmm_kernel<<<(N_POI_C + 3) / 4, 128>>>(F, prop, N_POI_C);
}

// round 6
// speedup vs baseline: 1.2397x; 1.0338x over previous
#include <cuda_runtime.h>
#include <cstdint>

#define N_POI_C  100000
#define N_EDGE_C 50000
#define NNZ_MAX  3200000
#define EMB      128
#define SCAN_B   1024

// ---------------- scratch: TWO independent CSR buffer sets (for stream overlap) ----
__device__ int   g_cnt0[N_EDGE_C];
__device__ int   g_rowptr0[N_EDGE_C + 1];
__device__ int   g_cursor0[N_EDGE_C];
__device__ int   g_bsum0[128];
__device__ int   g_boff0[129];
__device__ int2  g_pack0[NNZ_MAX];

__device__ int   g_cnt1[N_POI_C];
__device__ int   g_rowptr1[N_POI_C + 1];
__device__ int   g_cursor1[N_POI_C];
__device__ int   g_bsum1[128];
__device__ int   g_boff1[129];
__device__ int2  g_pack1[NNZ_MAX];

__device__ float g_S1[(size_t)N_EDGE_C * EMB];          // spmm(pte, poi_embs)
__device__ float g_Wc1[EMB * EMB];                      // W_poi  @ Wf[0:128]
__device__ float g_Wc2[EMB * EMB];                      // W_edge @ Wf[128:256]

template<int S> __device__ __forceinline__ int*  CNT()    { return S ? g_cnt1    : g_cnt0; }
template<int S> __device__ __forceinline__ int*  ROWPTR() { return S ? g_rowptr1 : g_rowptr0; }
template<int S> __device__ __forceinline__ int*  CURSOR() { return S ? g_cursor1 : g_cursor0; }
template<int S> __device__ __forceinline__ int*  BSUM()   { return S ? g_bsum1   : g_bsum0; }
template<int S> __device__ __forceinline__ int*  BOFF()   { return S ? g_boff1   : g_boff0; }
template<int S> __device__ __forceinline__ int2* PACK()   { return S ? g_pack1   : g_pack0; }

// ---------------- tiny weight-fold GEMMs: Wc1/Wc2 (128x128 each) ----------------
__global__ void wc_kernel(const float* __restrict__ Wp,
                          const float* __restrict__ We,
                          const float* __restrict__ Wf) {
    __shared__ float srow[EMB];
    int i = blockIdx.x;            // output row
    int j = threadIdx.x;           // output col
    const float* W  = blockIdx.y ? We : Wp;
    const float* Bf = Wf + (blockIdx.y ? EMB * EMB : 0);
    srow[j] = W[i * EMB + j];
    __syncthreads();
    float acc = 0.f;
#pragma unroll 8
    for (int k = 0; k < EMB; ++k)
        acc = fmaf(srow[k], Bf[k * EMB + j], acc);
    (blockIdx.y ? g_Wc2 : g_Wc1)[i * EMB + j] = acc;
}

// ---------------- CSR build ----------------
template<int S>
__global__ void zero_kernel(int n) {
    int* cnt = CNT<S>();
    for (int i = blockIdx.x * blockDim.x + threadIdx.x; i < n;
         i += gridDim.x * blockDim.x)
        cnt[i] = 0;
}

template<int S>
__global__ void hist_kernel(const int* __restrict__ rows, int nnz) {
    int* cnt = CNT<S>();
    int stride = gridDim.x * blockDim.x;
    int tid = blockIdx.x * blockDim.x + threadIdx.x;
    int n4 = nnz >> 2;
    const int4* r4 = (const int4*)rows;
    for (int i = tid; i < n4; i += stride) {
        int4 r = __ldg(r4 + i);
        atomicAdd(&cnt[r.x], 1);
        atomicAdd(&cnt[r.y], 1);
        atomicAdd(&cnt[r.z], 1);
        atomicAdd(&cnt[r.w], 1);
    }
    for (int i = n4 * 4 + tid; i < nnz; i += stride)
        atomicAdd(&cnt[rows[i]], 1);
}

// --- multi-block exclusive scan: 3 passes ---
template<int S>
__global__ __launch_bounds__(SCAN_B) void scan_pass1(int n) {
    __shared__ int ws[32];
    int tid = threadIdx.x, lane = tid & 31, wid = tid >> 5;
    int i = blockIdx.x * SCAN_B + tid;
    int s = (i < n) ? CNT<S>()[i] : 0;
#pragma unroll
    for (int d = 16; d > 0; d >>= 1) s += __shfl_down_sync(0xFFFFFFFFu, s, d);
    if (lane == 0) ws[wid] = s;
    __syncthreads();
    if (wid == 0) {
        int t = ws[lane];
#pragma unroll
        for (int d = 16; d > 0; d >>= 1) t += __shfl_down_sync(0xFFFFFFFFu, t, d);
        if (lane == 0) BSUM<S>()[blockIdx.x] = t;
    }
}

template<int S>
__global__ __launch_bounds__(128) void scan_pass2(int nblocks) {
    __shared__ int ws[4];
    int tid = threadIdx.x, lane = tid & 31, wid = tid >> 5;
    int v = (tid < nblocks) ? BSUM<S>()[tid] : 0;
    int x = v;
#pragma unroll
    for (int d = 1; d < 32; d <<= 1) {
        int t = __shfl_up_sync(0xFFFFFFFFu, x, d);
        if (lane >= d) x += t;
    }
    if (lane == 31) ws[wid] = x;
    __syncthreads();
    int woff = 0;
    for (int w = 0; w < wid; ++w) woff += ws[w];
    int incl = x + woff;
    if (tid < nblocks) {
        BOFF<S>()[tid] = incl - v;
        if (tid == nblocks - 1) BOFF<S>()[nblocks] = incl;
    }
}

template<int S>
__global__ __launch_bounds__(SCAN_B) void scan_pass3(int n) {
    __shared__ int ws[32];
    int tid = threadIdx.x, lane = tid & 31, wid = tid >> 5;
    int i = blockIdx.x * SCAN_B + tid;
    int v = (i < n) ? CNT<S>()[i] : 0;
    int x = v;
#pragma unroll
    for (int d = 1; d < 32; d <<= 1) {
        int t = __shfl_up_sync(0xFFFFFFFFu, x, d);
        if (lane >= d) x += t;
    }
    if (lane == 31) ws[wid] = x;
    __syncthreads();
    if (wid == 0) {
        int w = ws[lane];
#pragma unroll
        for (int d = 1; d < 32; d <<= 1) {
            int t = __shfl_up_sync(0xFFFFFFFFu, w, d);
            if (lane >= d) w += t;
        }
        ws[lane] = w;
    }
    __syncthreads();
    int woff = wid ? ws[wid - 1] : 0;
    int excl = (x - v) + woff + BOFF<S>()[blockIdx.x];
    if (i < n) {
        ROWPTR<S>()[i] = excl;
        CURSOR<S>()[i] = excl;
        if (i == n - 1) ROWPTR<S>()[n] = excl + v;
    }
}

template<int S>
__global__ void scatter_kernel(const int* __restrict__ rows,
                               const int* __restrict__ cols,
                               const float* __restrict__ vals, int nnz) {
    int*  cur  = CURSOR<S>();
    int2* pack = PACK<S>();
    int stride = gridDim.x * blockDim.x;
    int tid = blockIdx.x * blockDim.x + threadIdx.x;
    int n4 = nnz >> 2;
    const int4*   r4 = (const int4*)rows;
    const int4*   c4 = (const int4*)cols;
    const float4* v4 = (const float4*)vals;
    for (int i = tid; i < n4; i += stride) {
        int4 r = __ldg(r4 + i);
        int4 c = __ldg(c4 + i);
        float4 v = __ldg(v4 + i);
        int p0 = atomicAdd(&cur[r.x], 1);
        int p1 = atomicAdd(&cur[r.y], 1);
        int p2 = atomicAdd(&cur[r.z], 1);
        int p3 = atomicAdd(&cur[r.w], 1);
        pack[p0] = make_int2(c.x, __float_as_int(v.x));
        pack[p1] = make_int2(c.y, __float_as_int(v.y));
        pack[p2] = make_int2(c.z, __float_as_int(v.z));
        pack[p3] = make_int2(c.w, __float_as_int(v.w));
    }
    for (int i = n4 * 4 + tid; i < nnz; i += stride) {
        int pos = atomicAdd(&cur[rows[i]], 1);
        pack[pos] = make_int2(cols[i], __float_as_int(vals[i]));
    }
}

// ---------------- CSR SpMM: one warp per output row, float4 per lane ----------------
template<int S>
__global__ __launch_bounds__(128) void spmm_kernel(const float* __restrict__ dense,
                                                   float* __restrict__ out,
                                                   int nrows) {
    int r = blockIdx.x * 4 + (threadIdx.x >> 5);
    if (r >= nrows) return;
    int lane = threadIdx.x & 31;
    const int*  rowptr = ROWPTR<S>();
    const int2* pack   = PACK<S>();
    int s = __ldg(&rowptr[r]);
    int e = __ldg(&rowptr[r + 1]);
    float* o = out ? out : (float*)g_S1;
    float4 acc = make_float4(0.f, 0.f, 0.f, 0.f);
    int j = s;
    for (; j + 4 <= e; j += 4) {
        int2 p0 = __ldg(&pack[j + 0]);
        int2 p1 = __ldg(&pack[j + 1]);
        int2 p2 = __ldg(&pack[j + 2]);
        int2 p3 = __ldg(&pack[j + 3]);
        float4 d0 = __ldg((const float4*)(dense + (size_t)p0.x * EMB) + lane);
        float4 d1 = __ldg((const float4*)(dense + (size_t)p1.x * EMB) + lane);
        float4 d2 = __ldg((const float4*)(dense + (size_t)p2.x * EMB) + lane);
        float4 d3 = __ldg((const float4*)(dense + (size_t)p3.x * EMB) + lane);
        float v0 = __int_as_float(p0.y), v1 = __int_as_float(p1.y);
        float v2 = __int_as_float(p2.y), v3 = __int_as_float(p3.y);
        acc.x = fmaf(v0, d0.x, acc.x); acc.y = fmaf(v0, d0.y, acc.y);
        acc.z = fmaf(v0, d0.z, acc.z); acc.w = fmaf(v0, d0.w, acc.w);
        acc.x = fmaf(v1, d1.x, acc.x); acc.y = fmaf(v1, d1.y, acc.y);
        acc.z = fmaf(v1, d1.z, acc.z); acc.w = fmaf(v1, d1.w, acc.w);
        acc.x = fmaf(v2, d2.x, acc.x); acc.y = fmaf(v2, d2.y, acc.y);
        acc.z = fmaf(v2, d2.z, acc.z); acc.w = fmaf(v2, d2.w, acc.w);
        acc.x = fmaf(v3, d3.x, acc.x); acc.y = fmaf(v3, d3.y, acc.y);
        acc.z = fmaf(v3, d3.z, acc.z); acc.w = fmaf(v3, d3.w, acc.w);
    }
    for (; j < e; ++j) {
        int2 p = __ldg(&pack[j]);
        float4 d = __ldg((const float4*)(dense + (size_t)p.x * EMB) + lane);
        float v = __int_as_float(p.y);
        acc.x = fmaf(v, d.x, acc.x); acc.y = fmaf(v, d.y, acc.y);
        acc.z = fmaf(v, d.z, acc.z); acc.w = fmaf(v, d.w, acc.w);
    }
    *(float4*)(o + (size_t)r * EMB + lane * 4) = acc;
}

// ---------------- fused edge GEMM: F = g_S1 @ Wc1 + E @ Wc2 ----------------
// 64-row tiles, 256 threads, 8x4 microtile per thread, BK=32, K=256 (2 sources).
__global__ __launch_bounds__(256) void fused_gemm_kernel(const float* __restrict__ E,
                                                         float* __restrict__ F,
                                                         int nrows) {
    __shared__ __align__(16) float sA[32][68];   // transposed A chunk [k][m]; 68 keeps rows 16B-aligned
    __shared__ __align__(16) float sB[32][128];
    int tid = threadIdx.x;
    int tr = tid >> 5;          // row group 0..7 (8 rows each)
    int tc = tid & 31;          // col group 0..31 (4 cols each)
    int row0 = blockIdx.x * 64;
    float acc[8][4];
#pragma unroll
    for (int i = 0; i < 8; ++i)
#pragma unroll
        for (int c = 0; c < 4; ++c) acc[i][c] = 0.f;

#pragma unroll 1
    for (int chunk = 0; chunk < 8; ++chunk) {
        const float* A = (chunk < 4) ? (const float*)g_S1 : E;
        const float* B = (chunk < 4) ? (const float*)g_Wc1 : (const float*)g_Wc2;
        int k0 = (chunk & 3) * 32;
        // load 64x32 A chunk (transposed into sA)
#pragma unroll
        for (int q = 0; q < 2; ++q) {
            int lin = tid * 2 + q;          // 0..511
            int m   = lin >> 3;             // 0..63
            int kk  = (lin & 7) << 2;       // 0..28 step 4
            float4 a4 = make_float4(0.f, 0.f, 0.f, 0.f);
            if (row0 + m < nrows)
                a4 = *(const float4*)(A + (size_t)(row0 + m) * EMB + k0 + kk);
            sA[kk + 0][m] = a4.x; sA[kk + 1][m] = a4.y;
            sA[kk + 2][m] = a4.z; sA[kk + 3][m] = a4.w;
        }
        // load 32x128 B chunk
#pragma unroll
        for (int q = 0; q < 4; ++q) {
            int lin = tid * 4 + q;          // 0..1023 float4 slots
            int k = lin >> 5, c4 = lin & 31;
            *(float4*)(&sB[k][c4 * 4]) =
                *(const float4*)(B + (size_t)(k0 + k) * EMB + c4 * 4);
        }
        __syncthreads();
#pragma unroll
        for (int k = 0; k < 32; ++k) {
            float4 b  = *(const float4*)(&sB[k][tc * 4]);
            float4 a0 = *(const float4*)(&sA[k][tr * 8]);      // LDS.128 (broadcast within warp)
            float4 a1 = *(const float4*)(&sA[k][tr * 8 + 4]);
            float av[8] = {a0.x, a0.y, a0.z, a0.w, a1.x, a1.y, a1.z, a1.w};
#pragma unroll
            for (int i = 0; i < 8; ++i) {
                acc[i][0] = fmaf(av[i], b.x, acc[i][0]);
                acc[i][1] = fmaf(av[i], b.y, acc[i][1]);
                acc[i][2] = fmaf(av[i], b.z, acc[i][2]);
                acc[i][3] = fmaf(av[i], b.w, acc[i][3]);
            }
        }
        __syncthreads();
    }
#pragma unroll
    for (int i = 0; i < 8; ++i) {
        int r = row0 + tr * 8 + i;
        if (r < nrows)
            *(float4*)(F + (size_t)r * EMB + tc * 4) =
                make_float4(acc[i][0], acc[i][1], acc[i][2], acc[i][3]);
    }
}

// ---------------- launch ----------------
template<int S>
static inline void build_csr(const int* rows, const int* cols, const float* vals,
                             int nnz, int nrows, cudaStream_t st) {
    int nblocks = (nrows + SCAN_B - 1) / SCAN_B;
    zero_kernel<S><<<256, 256, 0, st>>>(nrows);
    hist_kernel<S><<<1024, 256, 0, st>>>(rows, nnz);
    scan_pass1<S><<<nblocks, SCAN_B, 0, st>>>(nrows);
    scan_pass2<S><<<1, 128, 0, st>>>(nblocks);
    scan_pass3<S><<<nblocks, SCAN_B, 0, st>>>(nrows);
    scatter_kernel<S><<<1024, 256, 0, st>>>(rows, cols, vals, nnz);
}

static cudaStream_t g_s2  = nullptr;
static cudaEvent_t  g_evF = nullptr;
static cudaEvent_t  g_evJ = nullptr;

extern "C" void kernel_launch(void* const* d_in, const int* in_sizes, int n_in,
                              void* d_out, int out_size) {
    const float* poi  = (const float*)d_in[0];
    const float* edge = (const float*)d_in[1];
    const int*   pr   = (const int*)d_in[2];
    const int*   pc   = (const int*)d_in[3];
    const float* pv   = (const float*)d_in[4];
    const int*   er   = (const int*)d_in[5];
    const int*   ec   = (const int*)d_in[6];
    const float* evv  = (const float*)d_in[7];
    const float* Wp   = (const float*)d_in[8];
    const float* We   = (const float*)d_in[9];
    const float* Wf   = (const float*)d_in[10];
    int nnz1 = in_sizes[2];
    int nnz2 = in_sizes[5];

    float* prop = (float*)d_out;                       // [100000, 128]
    float* F    = prop + (size_t)N_POI_C * EMB;        // [50000, 128]

    // one-time handle creation (no device memory; identical work every call)
    if (!g_s2) {
        cudaStreamCreateWithFlags(&g_s2, cudaStreamNonBlocking);
        cudaEventCreateWithFlags(&g_evF, cudaEventDisableTiming);
        cudaEventCreateWithFlags(&g_evJ, cudaEventDisableTiming);
    }

    // ---- fork: CSR build for etp (set 1) runs concurrently on g_s2 ----
    cudaEventRecord(g_evF, 0);
    cudaStreamWaitEvent(g_s2, g_evF, 0);
    build_csr<1>(er, ec, evv, nnz2, N_POI_C, g_s2);
    cudaEventRecord(g_evJ, g_s2);

    // ---- main stream: weights fold, CSR for pte (set 0), SpMM1, GEMM ----
    wc_kernel<<<dim3(128, 2), 128>>>(Wp, We, Wf);
    build_csr<0>(pr, pc, pv, nnz1, N_EDGE_C, 0);
    spmm_kernel<0><<<(N_EDGE_C + 3) / 4, 128>>>(poi, nullptr, N_EDGE_C);
    fused_gemm_kernel<<<(N_EDGE_C + 63) / 64, 256>>>(edge, F, N_EDGE_C);

    // ---- join, then SpMM2: prop = etp @ F ----
    cudaStreamWaitEvent(0, g_evJ, 0);
    spmm_kernel<1><<<(N_POI_C + 3) / 4, 128>>>(F, prop, N_POI_C);
}

// round 8
// speedup vs baseline: 1.2776x; 1.0306x over previous
#include <cuda_runtime.h>
#include <cstdint>

#define N_POI_C  100000
#define N_EDGE_C 50000
#define NNZ_MAX  3200000
#define EMB      128
#define SCAN_B   1024

// ---------------- scratch: TWO independent CSR buffer sets (for stream overlap) ----
__device__ int   g_cnt0[N_EDGE_C];
__device__ int   g_rowptr0[N_EDGE_C + 1];
__device__ int   g_cursor0[N_EDGE_C];
__device__ int   g_bsum0[128];
__device__ int   g_boff0[129];
__device__ int2  g_pack0[NNZ_MAX];

__device__ int   g_cnt1[N_POI_C];
__device__ int   g_rowptr1[N_POI_C + 1];
__device__ int   g_cursor1[N_POI_C];
__device__ int   g_bsum1[128];
__device__ int   g_boff1[129];
__device__ int2  g_pack1[NNZ_MAX];

__device__ float g_S1[(size_t)N_EDGE_C * EMB];          // spmm(pte, poi_embs)
__device__ float g_Wc1[EMB * EMB];                      // W_poi  @ Wf[0:128]
__device__ float g_Wc2[EMB * EMB];                      // W_edge @ Wf[128:256]

template<int S> __device__ __forceinline__ int*  CNT()    { return S ? g_cnt1    : g_cnt0; }
template<int S> __device__ __forceinline__ int*  ROWPTR() { return S ? g_rowptr1 : g_rowptr0; }
template<int S> __device__ __forceinline__ int*  CURSOR() { return S ? g_cursor1 : g_cursor0; }
template<int S> __device__ __forceinline__ int*  BSUM()   { return S ? g_bsum1   : g_bsum0; }
template<int S> __device__ __forceinline__ int*  BOFF()   { return S ? g_boff1   : g_boff0; }
template<int S> __device__ __forceinline__ int2* PACK()   { return S ? g_pack1   : g_pack0; }

// ---------------- tiny weight-fold GEMMs: Wc1/Wc2 (128x128 each) ----------------
__global__ void wc_kernel(const float* __restrict__ Wp,
                          const float* __restrict__ We,
                          const float* __restrict__ Wf) {
    __shared__ float srow[EMB];
    int i = blockIdx.x;            // output row
    int j = threadIdx.x;           // output col
    const float* W  = blockIdx.y ? We : Wp;
    const float* Bf = Wf + (blockIdx.y ? EMB * EMB : 0);
    srow[j] = W[i * EMB + j];
    __syncthreads();
    float acc = 0.f;
#pragma unroll 8
    for (int k = 0; k < EMB; ++k)
        acc = fmaf(srow[k], Bf[k * EMB + j], acc);
    (blockIdx.y ? g_Wc2 : g_Wc1)[i * EMB + j] = acc;
}

// ---------------- CSR build ----------------
template<int S>
__global__ void zero_kernel(int n) {
    int* cnt = CNT<S>();
    for (int i = blockIdx.x * blockDim.x + threadIdx.x; i < n;
         i += gridDim.x * blockDim.x)
        cnt[i] = 0;
}

template<int S>
__global__ void hist_kernel(const int* __restrict__ rows, int nnz) {
    int* cnt = CNT<S>();
    int stride = gridDim.x * blockDim.x;
    int tid = blockIdx.x * blockDim.x + threadIdx.x;
    int n4 = nnz >> 2;
    const int4* r4 = (const int4*)rows;
    for (int i = tid; i < n4; i += stride) {
        int4 r = __ldg(r4 + i);
        atomicAdd(&cnt[r.x], 1);
        atomicAdd(&cnt[r.y], 1);
        atomicAdd(&cnt[r.z], 1);
        atomicAdd(&cnt[r.w], 1);
    }
    for (int i = n4 * 4 + tid; i < nnz; i += stride)
        atomicAdd(&cnt[rows[i]], 1);
}

// --- multi-block exclusive scan: 3 passes ---
template<int S>
__global__ __launch_bounds__(SCAN_B) void scan_pass1(int n) {
    __shared__ int ws[32];
    int tid = threadIdx.x, lane = tid & 31, wid = tid >> 5;
    int i = blockIdx.x * SCAN_B + tid;
    int s = (i < n) ? CNT<S>()[i] : 0;
#pragma unroll
    for (int d = 16; d > 0; d >>= 1) s += __shfl_down_sync(0xFFFFFFFFu, s, d);
    if (lane == 0) ws[wid] = s;
    __syncthreads();
    if (wid == 0) {
        int t = ws[lane];
#pragma unroll
        for (int d = 16; d > 0; d >>= 1) t += __shfl_down_sync(0xFFFFFFFFu, t, d);
        if (lane == 0) BSUM<S>()[blockIdx.x] = t;
    }
}

template<int S>
__global__ __launch_bounds__(128) void scan_pass2(int nblocks) {
    __shared__ int ws[4];
    int tid = threadIdx.x, lane = tid & 31, wid = tid >> 5;
    int v = (tid < nblocks) ? BSUM<S>()[tid] : 0;
    int x = v;
#pragma unroll
    for (int d = 1; d < 32; d <<= 1) {
        int t = __shfl_up_sync(0xFFFFFFFFu, x, d);
        if (lane >= d) x += t;
    }
    if (lane == 31) ws[wid] = x;
    __syncthreads();
    int woff = 0;
    for (int w = 0; w < wid; ++w) woff += ws[w];
    int incl = x + woff;
    if (tid < nblocks) {
        BOFF<S>()[tid] = incl - v;
        if (tid == nblocks - 1) BOFF<S>()[nblocks] = incl;
    }
}

template<int S>
__global__ __launch_bounds__(SCAN_B) void scan_pass3(int n) {
    __shared__ int ws[32];
    int tid = threadIdx.x, lane = tid & 31, wid = tid >> 5;
    int i = blockIdx.x * SCAN_B + tid;
    int v = (i < n) ? CNT<S>()[i] : 0;
    int x = v;
#pragma unroll
    for (int d = 1; d < 32; d <<= 1) {
        int t = __shfl_up_sync(0xFFFFFFFFu, x, d);
        if (lane >= d) x += t;
    }
    if (lane == 31) ws[wid] = x;
    __syncthreads();
    if (wid == 0) {
        int w = ws[lane];
#pragma unroll
        for (int d = 1; d < 32; d <<= 1) {
            int t = __shfl_up_sync(0xFFFFFFFFu, w, d);
            if (lane >= d) w += t;
        }
        ws[lane] = w;
    }
    __syncthreads();
    int woff = wid ? ws[wid - 1] : 0;
    int excl = (x - v) + woff + BOFF<S>()[blockIdx.x];
    if (i < n) {
        ROWPTR<S>()[i] = excl;
        CURSOR<S>()[i] = excl;
        if (i == n - 1) ROWPTR<S>()[n] = excl + v;
    }
}

template<int S>
__global__ void scatter_kernel(const int* __restrict__ rows,
                               const int* __restrict__ cols,
                               const float* __restrict__ vals, int nnz) {
    int*  cur  = CURSOR<S>();
    int2* pack = PACK<S>();
    int stride = gridDim.x * blockDim.x;
    int tid = blockIdx.x * blockDim.x + threadIdx.x;
    int n4 = nnz >> 2;
    const int4*   r4 = (const int4*)rows;
    const int4*   c4 = (const int4*)cols;
    const float4* v4 = (const float4*)vals;
    for (int i = tid; i < n4; i += stride) {
        int4 r = __ldg(r4 + i);
        int4 c = __ldg(c4 + i);
        float4 v = __ldg(v4 + i);
        int p0 = atomicAdd(&cur[r.x], 1);
        int p1 = atomicAdd(&cur[r.y], 1);
        int p2 = atomicAdd(&cur[r.z], 1);
        int p3 = atomicAdd(&cur[r.w], 1);
        pack[p0] = make_int2(c.x, __float_as_int(v.x));
        pack[p1] = make_int2(c.y, __float_as_int(v.y));
        pack[p2] = make_int2(c.z, __float_as_int(v.z));
        pack[p3] = make_int2(c.w, __float_as_int(v.w));
    }
    for (int i = n4 * 4 + tid; i < nnz; i += stride) {
        int pos = atomicAdd(&cur[rows[i]], 1);
        pack[pos] = make_int2(cols[i], __float_as_int(vals[i]));
    }
}

// ---------------- CSR SpMM: one warp per output row, float4 per lane ----------------
template<int S>
__global__ __launch_bounds__(128) void spmm_kernel(const float* __restrict__ dense,
                                                   float* __restrict__ out,
                                                   int nrows) {
    int r = blockIdx.x * 4 + (threadIdx.x >> 5);
    if (r >= nrows) return;
    int lane = threadIdx.x & 31;
    const int*  rowptr = ROWPTR<S>();
    const int2* pack   = PACK<S>();
    int s = __ldg(&rowptr[r]);
    int e = __ldg(&rowptr[r + 1]);
    float* o = out ? out : (float*)g_S1;
    float4 acc = make_float4(0.f, 0.f, 0.f, 0.f);
    int j = s;
    for (; j + 4 <= e; j += 4) {
        int2 p0 = __ldg(&pack[j + 0]);
        int2 p1 = __ldg(&pack[j + 1]);
        int2 p2 = __ldg(&pack[j + 2]);
        int2 p3 = __ldg(&pack[j + 3]);
        float4 d0 = __ldg((const float4*)(dense + (size_t)p0.x * EMB) + lane);
        float4 d1 = __ldg((const float4*)(dense + (size_t)p1.x * EMB) + lane);
        float4 d2 = __ldg((const float4*)(dense + (size_t)p2.x * EMB) + lane);
        float4 d3 = __ldg((const float4*)(dense + (size_t)p3.x * EMB) + lane);
        float v0 = __int_as_float(p0.y), v1 = __int_as_float(p1.y);
        float v2 = __int_as_float(p2.y), v3 = __int_as_float(p3.y);
        acc.x = fmaf(v0, d0.x, acc.x); acc.y = fmaf(v0, d0.y, acc.y);
        acc.z = fmaf(v0, d0.z, acc.z); acc.w = fmaf(v0, d0.w, acc.w);
        acc.x = fmaf(v1, d1.x, acc.x); acc.y = fmaf(v1, d1.y, acc.y);
        acc.z = fmaf(v1, d1.z, acc.z); acc.w = fmaf(v1, d1.w, acc.w);
        acc.x = fmaf(v2, d2.x, acc.x); acc.y = fmaf(v2, d2.y, acc.y);
        acc.z = fmaf(v2, d2.z, acc.z); acc.w = fmaf(v2, d2.w, acc.w);
        acc.x = fmaf(v3, d3.x, acc.x); acc.y = fmaf(v3, d3.y, acc.y);
        acc.z = fmaf(v3, d3.z, acc.z); acc.w = fmaf(v3, d3.w, acc.w);
    }
    for (; j < e; ++j) {
        int2 p = __ldg(&pack[j]);
        float4 d = __ldg((const float4*)(dense + (size_t)p.x * EMB) + lane);
        float v = __int_as_float(p.y);
        acc.x = fmaf(v, d.x, acc.x); acc.y = fmaf(v, d.y, acc.y);
        acc.z = fmaf(v, d.z, acc.z); acc.w = fmaf(v, d.w, acc.w);
    }
    *(float4*)(o + (size_t)r * EMB + lane * 4) = acc;
}

// ---------------- split GEMM: MODE 0: F = E@Wc2 ; MODE 1: F += S1@Wc1 ----------------
// 64-row tiles, 256 threads, 8x4 microtile per thread, BK=32, K=128 (4 chunks).
template<int MODE>
__global__ __launch_bounds__(256) void gemm_kernel(const float* __restrict__ Ain,
                                                   float* __restrict__ F,
                                                   int nrows) {
    __shared__ __align__(16) float sA[32][68];   // transposed A chunk [k][m]
    __shared__ __align__(16) float sB[32][128];
    int tid = threadIdx.x;
    int tr = tid >> 5;          // row group 0..7 (8 rows each)
    int tc = tid & 31;          // col group 0..31 (4 cols each)
    int row0 = blockIdx.x * 64;
    const float* A = MODE ? (const float*)g_S1 : Ain;
    const float* B = MODE ? (const float*)g_Wc1 : (const float*)g_Wc2;

    float acc[8][4];
    if (MODE) {
#pragma unroll
        for (int i = 0; i < 8; ++i) {
            int r = row0 + tr * 8 + i;
            float4 c = (r < nrows)
                ? *(const float4*)(F + (size_t)r * EMB + tc * 4)
                : make_float4(0.f, 0.f, 0.f, 0.f);
            acc[i][0] = c.x; acc[i][1] = c.y; acc[i][2] = c.z; acc[i][3] = c.w;
        }
    } else {
#pragma unroll
        for (int i = 0; i < 8; ++i)
#pragma unroll
            for (int c = 0; c < 4; ++c) acc[i][c] = 0.f;
    }

#pragma unroll 1
    for (int chunk = 0; chunk < 4; ++chunk) {
        int k0 = chunk * 32;
        // load 64x32 A chunk (transposed into sA)
#pragma unroll
        for (int q = 0; q < 2; ++q) {
            int lin = tid * 2 + q;          // 0..511
            int m   = lin >> 3;             // 0..63
            int kk  = (lin & 7) << 2;       // 0..28 step 4
            float4 a4 = make_float4(0.f, 0.f, 0.f, 0.f);
            if (row0 + m < nrows)
                a4 = *(const float4*)(A + (size_t)(row0 + m) * EMB + k0 + kk);
            sA[kk + 0][m] = a4.x; sA[kk + 1][m] = a4.y;
            sA[kk + 2][m] = a4.z; sA[kk + 3][m] = a4.w;
        }
        // load 32x128 B chunk
#pragma unroll
        for (int q = 0; q < 4; ++q) {
            int lin = tid * 4 + q;          // 0..1023 float4 slots
            int k = lin >> 5, c4 = lin & 31;
            *(float4*)(&sB[k][c4 * 4]) =
                *(const float4*)(B + (size_t)(k0 + k) * EMB + c4 * 4);
        }
        __syncthreads();
#pragma unroll
        for (int k = 0; k < 32; ++k) {
            float4 b  = *(const float4*)(&sB[k][tc * 4]);
            float4 a0 = *(const float4*)(&sA[k][tr * 8]);
            float4 a1 = *(const float4*)(&sA[k][tr * 8 + 4]);
            float av[8] = {a0.x, a0.y, a0.z, a0.w, a1.x, a1.y, a1.z, a1.w};
#pragma unroll
            for (int i = 0; i < 8; ++i) {
                acc[i][0] = fmaf(av[i], b.x, acc[i][0]);
                acc[i][1] = fmaf(av[i], b.y, acc[i][1]);
                acc[i][2] = fmaf(av[i], b.z, acc[i][2]);
                acc[i][3] = fmaf(av[i], b.w, acc[i][3]);
            }
        }
        __syncthreads();
    }
#pragma unroll
    for (int i = 0; i < 8; ++i) {
        int r = row0 + tr * 8 + i;
        if (r < nrows)
            *(float4*)(F + (size_t)r * EMB + tc * 4) =
                make_float4(acc[i][0], acc[i][1], acc[i][2], acc[i][3]);
    }
}

// ---------------- launch ----------------
template<int S>
static inline void build_csr(const int* rows, const int* cols, const float* vals,
                             int nnz, int nrows, cudaStream_t st) {
    int nblocks = (nrows + SCAN_B - 1) / SCAN_B;
    zero_kernel<S><<<256, 256, 0, st>>>(nrows);
    hist_kernel<S><<<1024, 256, 0, st>>>(rows, nnz);
    scan_pass1<S><<<nblocks, SCAN_B, 0, st>>>(nrows);
    scan_pass2<S><<<1, 128, 0, st>>>(nblocks);
    scan_pass3<S><<<nblocks, SCAN_B, 0, st>>>(nrows);
    scatter_kernel<S><<<1024, 256, 0, st>>>(rows, cols, vals, nnz);
}

static cudaStream_t g_s2  = nullptr;   // CSR2 build
static cudaStream_t g_s3  = nullptr;   // gemmB (edge@Wc2)
static cudaEvent_t  g_evF  = nullptr;  // fork
static cudaEvent_t  g_evJ  = nullptr;  // CSR2 done
static cudaEvent_t  g_evWc = nullptr;  // wc done
static cudaEvent_t  g_evB  = nullptr;  // gemmB done

extern "C" void kernel_launch(void* const* d_in, const int* in_sizes, int n_in,
                              void* d_out, int out_size) {
    const float* poi  = (const float*)d_in[0];
    const float* edge = (const float*)d_in[1];
    const int*   pr   = (const int*)d_in[2];
    const int*   pc   = (const int*)d_in[3];
    const float* pv   = (const float*)d_in[4];
    const int*   er   = (const int*)d_in[5];
    const int*   ec   = (const int*)d_in[6];
    const float* evv  = (const float*)d_in[7];
    const float* Wp   = (const float*)d_in[8];
    const float* We   = (const float*)d_in[9];
    const float* Wf   = (const float*)d_in[10];
    int nnz1 = in_sizes[2];
    int nnz2 = in_sizes[5];

    float* prop = (float*)d_out;                       // [100000, 128]
    float* F    = prop + (size_t)N_POI_C * EMB;        // [50000, 128]

    if (!g_s2) {
        cudaStreamCreateWithFlags(&g_s2, cudaStreamNonBlocking);
        cudaStreamCreateWithFlags(&g_s3, cudaStreamNonBlocking);
        cudaEventCreateWithFlags(&g_evF,  cudaEventDisableTiming);
        cudaEventCreateWithFlags(&g_evJ,  cudaEventDisableTiming);
        cudaEventCreateWithFlags(&g_evWc, cudaEventDisableTiming);
        cudaEventCreateWithFlags(&g_evB,  cudaEventDisableTiming);
    }

    // ---- fork ----
    cudaEventRecord(g_evF, 0);

    // side stream A: CSR build for etp (set 1)
    cudaStreamWaitEvent(g_s2, g_evF, 0);
    build_csr<1>(er, ec, evv, nnz2, N_POI_C, g_s2);
    cudaEventRecord(g_evJ, g_s2);

    // main: fold weights first (gemmB needs Wc2)
    wc_kernel<<<dim3(128, 2), 128>>>(Wp, We, Wf);
    cudaEventRecord(g_evWc, 0);

    // side stream B: F = edge @ Wc2 (independent of SpMM1)
    cudaStreamWaitEvent(g_s3, g_evWc, 0);
    gemm_kernel<0><<<(N_EDGE_C + 63) / 64, 256, 0, g_s3>>>(edge, F, N_EDGE_C);
    cudaEventRecord(g_evB, g_s3);

    // main: CSR for pte (set 0), SpMM1 -> S1
    build_csr<0>(pr, pc, pv, nnz1, N_EDGE_C, 0);
    spmm_kernel<0><<<(N_EDGE_C + 3) / 4, 128>>>(poi, nullptr, N_EDGE_C);

    // main: F += S1 @ Wc1 (needs gemmB done)
    cudaStreamWaitEvent(0, g_evB, 0);
    gemm_kernel<1><<<(N_EDGE_C + 63) / 64, 256>>>(nullptr, F, N_EDGE_C);

    // join CSR2, then SpMM2: prop = etp @ F
    cudaStreamWaitEvent(0, g_evJ, 0);
    spmm_kernel<1><<<(N_POI_C + 3) / 4, 128>>>(F, prop, N_POI_C);
}